// round 8
// baseline (speedup 1.0000x reference)
#include <cuda_runtime.h>
#include <cstdint>
#include <math.h>

#define B_ 32
#define T_ 2048
#define D_ 1024
#define A_ 1024

// ---------------- scratch (device globals; no allocations allowed) ----------
__device__ float g_ws[B_ * A_];        // W_a_s : [B, A]
__device__ float g_scores[B_ * T_];    // pre-softmax scores, then exp(scores)
__device__ float g_Z[B_];              // softmax denominators

// ---------------- helpers ---------------------------------------------------
__device__ __forceinline__ uint32_t f2tf32(float x) {
    uint32_t u;
    asm("cvt.rna.tf32.f32 %0, %1;" : "=r"(u) : "f"(x));
    return u;
}

__device__ __forceinline__ void mma_tf32(float c[4], const uint32_t a[4],
                                         const uint32_t b[2]) {
    asm volatile(
        "mma.sync.aligned.m16n8k8.row.col.f32.tf32.tf32.f32 "
        "{%0,%1,%2,%3}, {%4,%5,%6,%7}, {%8,%9}, {%0,%1,%2,%3};\n"
        : "+f"(c[0]), "+f"(c[1]), "+f"(c[2]), "+f"(c[3])
        : "r"(a[0]), "r"(a[1]), "r"(a[2]), "r"(a[3]), "r"(b[0]), "r"(b[1]));
}

// ---------------- kernel 1: ws = s @ W_a ; zero scores ----------------------
// grid (A/128, B), block 128
__global__ void k1_ws(const float* __restrict__ s, const float* __restrict__ W) {
    int b = blockIdx.y;
    int a = blockIdx.x * 128 + threadIdx.x;
    __shared__ float sS[D_];
    for (int i = threadIdx.x; i < D_; i += 128) sS[i] = s[b * D_ + i];
    __syncthreads();
    float acc = 0.f;
#pragma unroll 8
    for (int d = 0; d < D_; d++) acc += sS[d] * W[d * A_ + a];
    g_ws[b * A_ + a] = acc;
    // zero the score accumulator (65536 floats, 32768 threads -> 2 each)
    int gid = (blockIdx.y * gridDim.x + blockIdx.x) * 128 + threadIdx.x;
    g_scores[gid] = 0.f;
    g_scores[gid + 32768] = 0.f;
}

// ---------------- kernel 2: fused scores GEMM --------------------------------
// scores[b,t] += sum_{a in Ntile} tanh(ws[b,a] + sum_d h[b,t,d]*U[d,a]) * v[a]
// CTA tile: M=128 (bt) x N=64 (a), K chunks of 32 over D.
// 8 warps (4 along M x 2 along N), each warp 32x32 via 2x4 m16n8k8 tf32 mma.
#define SA 36   // A smem row stride (uint32)
#define SB 68   // B smem row stride (uint32)
#define K2_SMEM 55808

__global__ void __launch_bounds__(256, 2)
k2_scores(const float* __restrict__ h, const float* __restrict__ U,
          const float* __restrict__ v) {
    extern __shared__ char smem[];
    uint32_t* As = (uint32_t*)smem;                 // [2][128*SA]
    uint32_t* Bs = (uint32_t*)(smem + 36864);       // [2][32*SB]
    float*    red = (float*)(smem + 54272);         // [2][128]
    float*    wsv = (float*)(smem + 55296);         // ws[64] | v[64]

    const int tid = threadIdx.x;
    const int n0 = blockIdx.x * 64;
    const int r0 = blockIdx.y * 128;          // global row = b*T + t
    const int b = r0 >> 11;                   // T = 2048

    const int warp = tid >> 5, lane = tid & 31;
    const int wm = warp & 3, wn = warp >> 2;  // warp coords: 4 x 2
    const int gid = lane >> 2, tg = lane & 3;

    float acc[2][4][4];
#pragma unroll
    for (int mt = 0; mt < 2; mt++)
#pragma unroll
        for (int nt = 0; nt < 4; nt++)
#pragma unroll
            for (int i = 0; i < 4; i++) acc[mt][nt][i] = 0.f;

    const float* hA = h + (size_t)r0 * D_;
    const float* UB = U + n0;

    float4 areg[4];
    float4 breg[2];

    // A staging: 4 float4/thread: idx=j*256+tid -> row=idx/8, cv=idx%8
    // B staging: 2 float4/thread: idx=j*256+tid -> k=idx/16, cv=idx%16
#define LOADG(k0)                                                           \
    {                                                                       \
        _Pragma("unroll") for (int j = 0; j < 4; j++) {                     \
            int idx = j * 256 + tid;                                        \
            int row = idx >> 3, cv = idx & 7;                               \
            areg[j] = *(const float4*)(hA + (size_t)row * D_ + (k0) + cv * 4); \
        }                                                                   \
        _Pragma("unroll") for (int j = 0; j < 2; j++) {                     \
            int idx = j * 256 + tid;                                        \
            int k = idx >> 4, cv = idx & 15;                                \
            breg[j] = *(const float4*)(UB + (size_t)((k0) + k) * A_ + cv * 4); \
        }                                                                   \
    }

#define STORES(buf)                                                         \
    {                                                                       \
        uint32_t* Ab = As + (buf) * (128 * SA);                             \
        uint32_t* Bb = Bs + (buf) * (32 * SB);                              \
        _Pragma("unroll") for (int j = 0; j < 4; j++) {                     \
            int idx = j * 256 + tid;                                        \
            int row = idx >> 3, cv = idx & 7;                               \
            uint32_t* p = Ab + row * SA + cv * 4;                           \
            p[0] = f2tf32(areg[j].x); p[1] = f2tf32(areg[j].y);             \
            p[2] = f2tf32(areg[j].z); p[3] = f2tf32(areg[j].w);             \
        }                                                                   \
        _Pragma("unroll") for (int j = 0; j < 2; j++) {                     \
            int idx = j * 256 + tid;                                        \
            int k = idx >> 4, cv = idx & 15;                                \
            uint32_t* p = Bb + k * SB + cv * 4;                             \
            p[0] = f2tf32(breg[j].x); p[1] = f2tf32(breg[j].y);             \
            p[2] = f2tf32(breg[j].z); p[3] = f2tf32(breg[j].w);             \
        }                                                                   \
    }

    LOADG(0);
    STORES(0);
    __syncthreads();

    const int NCHUNK = D_ / 32;  // 32
    for (int c = 0; c < NCHUNK; c++) {
        int buf = c & 1;
        if (c + 1 < NCHUNK) LOADG((c + 1) * 32);

        const uint32_t* Ab = As + buf * (128 * SA) + (wm * 32) * SA;
        const uint32_t* Bb = Bs + buf * (32 * SB) + wn * 32;
#pragma unroll
        for (int kk = 0; kk < 4; kk++) {
            const int kc = kk * 8;
            uint32_t af[2][4];
#pragma unroll
            for (int mt = 0; mt < 2; mt++) {
                int rb = mt * 16 + gid;
                af[mt][0] = Ab[rb * SA + kc + tg];
                af[mt][1] = Ab[(rb + 8) * SA + kc + tg];
                af[mt][2] = Ab[rb * SA + kc + tg + 4];
                af[mt][3] = Ab[(rb + 8) * SA + kc + tg + 4];
            }
            uint32_t bf[4][2];
#pragma unroll
            for (int nt = 0; nt < 4; nt++) {
                bf[nt][0] = Bb[(kc + tg) * SB + nt * 8 + gid];
                bf[nt][1] = Bb[(kc + tg + 4) * SB + nt * 8 + gid];
            }
#pragma unroll
            for (int mt = 0; mt < 2; mt++)
#pragma unroll
                for (int nt = 0; nt < 4; nt++)
                    mma_tf32(acc[mt][nt], af[mt], bf[nt]);
        }
        __syncthreads();
        if (c + 1 < NCHUNK) STORES(1 - buf);
        __syncthreads();
    }

    // ---- epilogue: tanh(ws + acc) * v, reduce over the 64 local columns ----
    if (tid < 64) wsv[tid] = g_ws[b * A_ + n0 + tid];
    else if (tid < 128) wsv[tid] = v[n0 + tid - 64];
    __syncthreads();

    float rsum[2][2] = {{0.f, 0.f}, {0.f, 0.f}};  // [mt][row-half]
#pragma unroll
    for (int mt = 0; mt < 2; mt++)
#pragma unroll
        for (int nt = 0; nt < 4; nt++)
#pragma unroll
            for (int i = 0; i < 4; i++) {
                int col = wn * 32 + nt * 8 + tg * 2 + (i & 1);
                float val = tanhf(acc[mt][nt][i] + wsv[col]) * wsv[64 + col];
                rsum[mt][i >> 1] += val;
            }
#pragma unroll
    for (int mt = 0; mt < 2; mt++)
#pragma unroll
        for (int hh = 0; hh < 2; hh++) {
            float r = rsum[mt][hh];
            r += __shfl_xor_sync(0xFFFFFFFF, r, 1);
            r += __shfl_xor_sync(0xFFFFFFFF, r, 2);
            rsum[mt][hh] = r;
        }
    if (tg == 0) {
#pragma unroll
        for (int mt = 0; mt < 2; mt++)
#pragma unroll
            for (int hh = 0; hh < 2; hh++) {
                int row = wm * 32 + mt * 16 + hh * 8 + gid;
                red[wn * 128 + row] = rsum[mt][hh];
            }
    }
    __syncthreads();
    if (tid < 128) atomicAdd(&g_scores[r0 + tid], red[tid] + red[128 + tid]);
}

// ---------------- kernel 3: exp + denominator; zero output -------------------
// grid 32 (one block per batch), block 256
__global__ void k3_softmax(float* __restrict__ c) {
    int b = blockIdx.x;
    int tid = threadIdx.x;
    float sum = 0.f;
    for (int t = tid; t < T_; t += 256) {
        float e = expf(g_scores[b * T_ + t]);
        g_scores[b * T_ + t] = e;
        sum += e;
    }
    __shared__ float rs[256];
    rs[tid] = sum;
    __syncthreads();
    for (int s2 = 128; s2; s2 >>= 1) {
        if (tid < s2) rs[tid] += rs[tid + s2];
        __syncthreads();
    }
    if (tid == 0) g_Z[b] = rs[0];
    for (int i = tid; i < D_; i += 256) c[b * D_ + i] = 0.f;
}

// ---------------- kernel 4: c = sum_t exp(e)/Z * h ---------------------------
// grid (D/128, B, 4 t-splits), block 128
__global__ void k4_context(const float* __restrict__ h, float* __restrict__ c) {
    int dd = blockIdx.x * 128 + threadIdx.x;
    int b = blockIdx.y;
    int t0 = blockIdx.z * (T_ / 4);
    float invZ = 1.0f / g_Z[b];
    const float* hp = h + ((size_t)(b * T_ + t0)) * D_ + dd;
    const float* sp = g_scores + b * T_ + t0;
    float acc = 0.f;
#pragma unroll 8
    for (int t = 0; t < T_ / 4; t++) {
        acc += sp[t] * hp[(size_t)t * D_];
    }
    atomicAdd(&c[b * D_ + dd], acc * invZ);
}

// ---------------- launch -----------------------------------------------------
extern "C" void kernel_launch(void* const* d_in, const int* in_sizes, int n_in,
                              void* d_out, int out_size) {
    const float* s = (const float*)d_in[0];
    const float* h = (const float*)d_in[1];
    const float* W = (const float*)d_in[2];
    const float* U = (const float*)d_in[3];
    const float* v = (const float*)d_in[4];
    float* c = (float*)d_out;

    cudaFuncSetAttribute(k2_scores, cudaFuncAttributeMaxDynamicSharedMemorySize,
                         K2_SMEM);

    k1_ws<<<dim3(A_ / 128, B_), 128>>>(s, W);
    k2_scores<<<dim3(A_ / 64, (B_ * T_) / 128), 256, K2_SMEM>>>(h, U, v);
    k3_softmax<<<B_, 256>>>(c);
    k4_context<<<dim3(D_ / 128, B_, 4), 128>>>(h, c);
}

// round 10
// speedup vs baseline: 1.2769x; 1.2769x over previous
#include <cuda_runtime.h>
#include <cstdint>
#include <math.h>

#define B_ 32
#define T_ 2048
#define D_ 1024
#define A_ 1024

// ---------------- scratch (device globals; no allocations allowed) ----------
__device__ float g_ws[B_ * A_];        // W_a_s : [B, A]
__device__ float g_scores[B_ * T_];    // pre-softmax scores, then exp(scores)
__device__ float g_Z[B_];              // softmax denominators

// ---------------- helpers ---------------------------------------------------
__device__ __forceinline__ uint32_t f2tf32(float x) {
    uint32_t u;
    asm("cvt.rna.tf32.f32 %0, %1;" : "=r"(u) : "f"(x));
    return u;
}

__device__ __forceinline__ void mma_tf32(float c[4], const uint32_t a[4],
                                         const uint32_t b[2]) {
    asm volatile(
        "mma.sync.aligned.m16n8k8.row.col.f32.tf32.tf32.f32 "
        "{%0,%1,%2,%3}, {%4,%5,%6,%7}, {%8,%9}, {%0,%1,%2,%3};\n"
        : "+f"(c[0]), "+f"(c[1]), "+f"(c[2]), "+f"(c[3])
        : "r"(a[0]), "r"(a[1]), "r"(a[2]), "r"(a[3]), "r"(b[0]), "r"(b[1]));
}

// ---------------- kernel 1: ws = s @ W_a ; zero scores ----------------------
// grid (A/128, B), block 128
__global__ void k1_ws(const float* __restrict__ s, const float* __restrict__ W) {
    int b = blockIdx.y;
    int a = blockIdx.x * 128 + threadIdx.x;
    __shared__ float sS[D_];
    for (int i = threadIdx.x; i < D_; i += 128) sS[i] = s[b * D_ + i];
    __syncthreads();
    float acc = 0.f;
#pragma unroll 8
    for (int d = 0; d < D_; d++) acc += sS[d] * W[d * A_ + a];
    g_ws[b * A_ + a] = acc;
    // zero the score accumulator (65536 floats, 32768 threads -> 2 each)
    int gid = (blockIdx.y * gridDim.x + blockIdx.x) * 128 + threadIdx.x;
    g_scores[gid] = 0.f;
    g_scores[gid + 32768] = 0.f;
}

// ---------------- kernel 2: fused scores GEMM --------------------------------
// CTA tile: M=64 (bt rows) x N=256 (a cols), K chunks of 16 over D.
// Rationale: N=256 -> h re-read only 4x (1.07 GB total) vs 16x before.
// 8 warps (2 along M x 4 along N), warp tile 32x64 = 2mt x 8nt m16n8k8 tf32.
#define SA 20    // A smem row stride (words): conflict-free for 8row x 4k frag
#define SB 264   // B smem row stride (words): banks 8k+n all distinct
#define KC 16
#define NCH (D_ / KC)            // 64 chunks
#define AS_BYTES (2 * 64 * SA * 4)      // 10240
#define BS_BYTES (2 * KC * SB * 4)      // 33792
#define RED_OFF  (AS_BYTES + BS_BYTES)  // 44032
#define WSV_OFF  (RED_OFF + 1024)       // 45056
#define K2_SMEM  (WSV_OFF + 2048)       // 47104

__global__ void __launch_bounds__(256, 2)
k2_scores(const float* __restrict__ h, const float* __restrict__ U,
          const float* __restrict__ v) {
    extern __shared__ char smem[];
    uint32_t* As = (uint32_t*)smem;                  // [2][64*SA]
    uint32_t* Bs = (uint32_t*)(smem + AS_BYTES);     // [2][KC*SB]
    float*    red = (float*)(smem + RED_OFF);        // [4][64]
    float*    wsv = (float*)(smem + WSV_OFF);        // ws[256] | v[256]

    const int tid = threadIdx.x;
    const int n0 = blockIdx.x * 256;
    const int r0 = blockIdx.y * 64;           // global row = b*T + t
    const int b = r0 >> 11;                   // T = 2048

    const int warp = tid >> 5, lane = tid & 31;
    const int wm = warp & 1, wn = warp >> 1;  // warp coords: 2 (M) x 4 (N)
    const int gid = lane >> 2, tg = lane & 3;

    float acc[2][8][4];
#pragma unroll
    for (int mt = 0; mt < 2; mt++)
#pragma unroll
        for (int nt = 0; nt < 8; nt++)
#pragma unroll
            for (int i = 0; i < 4; i++) acc[mt][nt][i] = 0.f;

    const float* hA = h + (size_t)r0 * D_;
    const float* UB = U + n0;

    float4 areg;       // A: 64*16 = 1024 el = 256 f4 -> 1 per thread
    float4 breg[4];    // B: 16*256 = 4096 el = 1024 f4 -> 4 per thread

    // A staging: tid -> row=tid>>2 (0..63), c4=tid&3 (k-offset in float4)
    // B staging: idx=j*256+tid -> k=idx>>6 (0..15), c4=idx&63 (n-offset in f4)
#define LOADG(k0)                                                            \
    {                                                                        \
        {                                                                    \
            int row = tid >> 2, c4 = tid & 3;                                \
            areg = *(const float4*)(hA + (size_t)row * D_ + (k0) + c4 * 4);  \
        }                                                                    \
        _Pragma("unroll") for (int j = 0; j < 4; j++) {                      \
            int idx = j * 256 + tid;                                         \
            int k = idx >> 6, c4 = idx & 63;                                 \
            breg[j] = *(const float4*)(UB + (size_t)((k0) + k) * A_ + c4 * 4); \
        }                                                                    \
    }

#define STORES(buf)                                                          \
    {                                                                        \
        uint32_t* Ab = As + (buf) * (64 * SA);                               \
        uint32_t* Bb = Bs + (buf) * (KC * SB);                               \
        {                                                                    \
            int row = tid >> 2, c4 = tid & 3;                                \
            uint32_t* p = Ab + row * SA + c4 * 4;                            \
            p[0] = f2tf32(areg.x); p[1] = f2tf32(areg.y);                    \
            p[2] = f2tf32(areg.z); p[3] = f2tf32(areg.w);                    \
        }                                                                    \
        _Pragma("unroll") for (int j = 0; j < 4; j++) {                      \
            int idx = j * 256 + tid;                                         \
            int k = idx >> 6, c4 = idx & 63;                                 \
            uint32_t* p = Bb + k * SB + c4 * 4;                              \
            p[0] = f2tf32(breg[j].x); p[1] = f2tf32(breg[j].y);              \
            p[2] = f2tf32(breg[j].z); p[3] = f2tf32(breg[j].w);              \
        }                                                                    \
    }

    LOADG(0);
    STORES(0);
    __syncthreads();

    for (int c = 0; c < NCH; c++) {
        int buf = c & 1;
        if (c + 1 < NCH) LOADG((c + 1) * KC);

        const uint32_t* Ab = As + buf * (64 * SA) + (wm * 32) * SA;
        const uint32_t* Bb = Bs + buf * (KC * SB) + wn * 64;
#pragma unroll
        for (int kk = 0; kk < 2; kk++) {
            const int kc = kk * 8;
            uint32_t af[2][4];
#pragma unroll
            for (int mt = 0; mt < 2; mt++) {
                int rb = mt * 16 + gid;
                af[mt][0] = Ab[rb * SA + kc + tg];
                af[mt][1] = Ab[(rb + 8) * SA + kc + tg];
                af[mt][2] = Ab[rb * SA + kc + tg + 4];
                af[mt][3] = Ab[(rb + 8) * SA + kc + tg + 4];
            }
            uint32_t bf[8][2];
#pragma unroll
            for (int nt = 0; nt < 8; nt++) {
                bf[nt][0] = Bb[(kc + tg) * SB + nt * 8 + gid];
                bf[nt][1] = Bb[(kc + tg + 4) * SB + nt * 8 + gid];
            }
#pragma unroll
            for (int mt = 0; mt < 2; mt++)
#pragma unroll
                for (int nt = 0; nt < 8; nt++)
                    mma_tf32(acc[mt][nt], af[mt], bf[nt]);
        }
        __syncthreads();
        if (c + 1 < NCH) STORES(1 - buf);
        __syncthreads();
    }

    // ---- epilogue: tanh(ws + acc) * v, reduce over the 256 local columns ---
    wsv[tid] = g_ws[b * A_ + n0 + tid];
    wsv[256 + tid] = v[n0 + tid];
    __syncthreads();

    float rsum[2][2] = {{0.f, 0.f}, {0.f, 0.f}};  // [mt][row-half]
#pragma unroll
    for (int mt = 0; mt < 2; mt++)
#pragma unroll
        for (int nt = 0; nt < 8; nt++)
#pragma unroll
            for (int i = 0; i < 4; i++) {
                int col = wn * 64 + nt * 8 + tg * 2 + (i & 1);
                float val = tanhf(acc[mt][nt][i] + wsv[col]) * wsv[256 + col];
                rsum[mt][i >> 1] += val;
            }
#pragma unroll
    for (int mt = 0; mt < 2; mt++)
#pragma unroll
        for (int hh = 0; hh < 2; hh++) {
            float r = rsum[mt][hh];
            r += __shfl_xor_sync(0xFFFFFFFF, r, 1);
            r += __shfl_xor_sync(0xFFFFFFFF, r, 2);
            rsum[mt][hh] = r;
        }
    if (tg == 0) {
#pragma unroll
        for (int mt = 0; mt < 2; mt++)
#pragma unroll
            for (int hh = 0; hh < 2; hh++) {
                int row = wm * 32 + mt * 16 + hh * 8 + gid;
                red[wn * 64 + row] = rsum[mt][hh];
            }
    }
    __syncthreads();
    if (tid < 64) {
        float sum = red[tid] + red[64 + tid] + red[128 + tid] + red[192 + tid];
        atomicAdd(&g_scores[r0 + tid], sum);
    }
}

// ---------------- kernel 3: exp + denominator; zero output -------------------
// grid 32 (one block per batch), block 256
__global__ void k3_softmax(float* __restrict__ c) {
    int b = blockIdx.x;
    int tid = threadIdx.x;
    float sum = 0.f;
    for (int t = tid; t < T_; t += 256) {
        float e = expf(g_scores[b * T_ + t]);
        g_scores[b * T_ + t] = e;
        sum += e;
    }
    __shared__ float rs[256];
    rs[tid] = sum;
    __syncthreads();
    for (int s2 = 128; s2; s2 >>= 1) {
        if (tid < s2) rs[tid] += rs[tid + s2];
        __syncthreads();
    }
    if (tid == 0) g_Z[b] = rs[0];
    for (int i = tid; i < D_; i += 256) c[b * D_ + i] = 0.f;
}

// ---------------- kernel 4: c = sum_t exp(e)/Z * h ---------------------------
// grid (D/128, B, 8 t-splits), block 128
__global__ void k4_context(const float* __restrict__ h, float* __restrict__ c) {
    int dd = blockIdx.x * 128 + threadIdx.x;
    int b = blockIdx.y;
    int t0 = blockIdx.z * (T_ / 8);
    float invZ = 1.0f / g_Z[b];
    const float* hp = h + ((size_t)(b * T_ + t0)) * D_ + dd;
    const float* sp = g_scores + b * T_ + t0;
    float acc0 = 0.f, acc1 = 0.f;
#pragma unroll 4
    for (int t = 0; t < T_ / 8; t += 2) {
        acc0 += sp[t] * hp[(size_t)t * D_];
        acc1 += sp[t + 1] * hp[(size_t)(t + 1) * D_];
    }
    atomicAdd(&c[b * D_ + dd], (acc0 + acc1) * invZ);
}

// ---------------- launch -----------------------------------------------------
extern "C" void kernel_launch(void* const* d_in, const int* in_sizes, int n_in,
                              void* d_out, int out_size) {
    const float* s = (const float*)d_in[0];
    const float* h = (const float*)d_in[1];
    const float* W = (const float*)d_in[2];
    const float* U = (const float*)d_in[3];
    const float* v = (const float*)d_in[4];
    float* c = (float*)d_out;

    cudaFuncSetAttribute(k2_scores, cudaFuncAttributeMaxDynamicSharedMemorySize,
                         K2_SMEM);

    k1_ws<<<dim3(A_ / 128, B_), 128>>>(s, W);
    k2_scores<<<dim3(A_ / 256, (B_ * T_) / 64), 256, K2_SMEM>>>(h, U, v);
    k3_softmax<<<B_, 256>>>(c);
    k4_context<<<dim3(D_ / 128, B_, 8), 128>>>(h, c);
}